// round 14
// baseline (speedup 1.0000x reference)
#include <cuda_runtime.h>
#include <cuda_fp16.h>
#include <cstdint>

#define NN 50000
#define EE 800000
#define CC 256
#define HH 8
#define DD 32
#define FF 512
#define SCALE 0.17677669529663689f

#define W_QKV 0
#define W_WO  196608
#define W_F1  262144
#define W_F2  393216
#define W_TOT 524288

// ---------------- scratch ----------------
__device__ float g_Q[(size_t)NN * CC];            // Q fp32
__device__ __half g_KV[(size_t)NN * 512];         // K|V fp16 packed per node
__device__ float g_h1[(size_t)NN * CC];           // ln1 out fp32
__device__ __half g_Xf[(size_t)NN * CC];          // x fp16
__device__ __half g_Af[(size_t)NN * CC];          // attn agg fp16
__device__ __half g_Hf[(size_t)NN * CC];          // h1 fp16
__device__ __half g_Tf[(size_t)NN * FF];          // ffn hidden fp16
__device__ __half g_W[W_TOT];                     // weights fp16, k-major
__device__ int g_cnt[NN], g_ofs[NN], g_cur[NN];
__device__ int g_ss[EE];                          // src sorted by dst

// ---------------- helpers ----------------
__device__ __forceinline__ uint32_t smem_u32(const void* p) {
    uint32_t a;
    asm("{ .reg .u64 t; cvta.to.shared.u64 t, %1; cvt.u32.u64 %0, t; }" : "=r"(a) : "l"(p));
    return a;
}
#define SWZ(off) ((off) ^ (((off) >> 3) & 0x70))

__device__ __forceinline__ void ldm_x4(uint32_t* r, uint32_t addr) {
    asm volatile("ldmatrix.sync.aligned.m8n8.x4.shared.b16 {%0,%1,%2,%3}, [%4];"
        : "=r"(r[0]), "=r"(r[1]), "=r"(r[2]), "=r"(r[3]) : "r"(addr));
}
__device__ __forceinline__ void mma_f16(float* d, const uint32_t* a, const uint32_t* b) {
    asm volatile("mma.sync.aligned.m16n8k16.row.col.f32.f16.f16.f32 "
        "{%0,%1,%2,%3}, {%4,%5,%6,%7}, {%8,%9}, {%0,%1,%2,%3};"
        : "+f"(d[0]), "+f"(d[1]), "+f"(d[2]), "+f"(d[3])
        : "r"(a[0]), "r"(a[1]), "r"(a[2]), "r"(a[3]), "r"(b[0]), "r"(b[1]));
}
__device__ __forceinline__ uint32_t f2h2(float x, float y) {
    __half2 h = __float22half2_rn(make_float2(x, y));
    return *(uint32_t*)&h;
}
__device__ __forceinline__ void cpa16(uint32_t dst, const void* src, uint32_t sz) {
    asm volatile("cp.async.cg.shared.global [%0], [%1], 16, %2;"
        :: "r"(dst), "l"(src), "r"(sz) : "memory");
}
#define CP_COMMIT() asm volatile("cp.async.commit_group;" ::: "memory")
#define CP_WAIT1()  asm volatile("cp.async.wait_group 1;" ::: "memory")

// unpack 8 fp16 (uint4) -> 8 floats
__device__ __forceinline__ void h8_to_f(const uint4& r, float* f) {
    float2 t;
    t = __half22float2(*(const __half2*)&r.x); f[0] = t.x; f[1] = t.y;
    t = __half22float2(*(const __half2*)&r.y); f[2] = t.x; f[3] = t.y;
    t = __half22float2(*(const __half2*)&r.z); f[4] = t.x; f[5] = t.y;
    t = __half22float2(*(const __half2*)&r.w); f[6] = t.x; f[7] = t.y;
}

// ---------------- weight prep (split: QKV slice / rest) ----------------
__global__ void prep_qkv(const float* __restrict__ Wq, const float* __restrict__ Wk,
                         const float* __restrict__ Wv)
{
    int idx = blockIdx.x * 256 + threadIdx.x;
    if (idx >= W_WO) return;
    int n = idx >> 8, k = idx & 255;
    float w;
    if (n < 256)      w = Wq[k * 256 + n];
    else if (n < 512) w = Wk[k * 256 + (n - 256)];
    else              w = Wv[k * 256 + (n - 512)];
    g_W[idx] = __float2half(w);
}
__global__ void prep_rest(const float* __restrict__ Wo, const float* __restrict__ F1,
                          const float* __restrict__ F2)
{
    int idx = W_WO + blockIdx.x * 256 + threadIdx.x;
    if (idx >= W_TOT) return;
    float w;
    if (idx < W_F1) {
        int l = idx - W_WO;
        int n = l >> 8, k = l & 255;
        w = Wo[k * 256 + n];
    } else if (idx < W_F2) {
        int l = idx - W_F1;
        int n = l >> 8, k = l & 255;
        w = F1[k * 512 + n];
    } else {
        int l = idx - W_F2;
        int n = l >> 9, k = l & 511;
        w = F2[k * 256 + n];
    }
    g_W[idx] = __float2half(w);
}

// ---------------- fp32 -> fp16 convert (vectorized) ----------------
__global__ void conv_f16(const float* __restrict__ in, __half* __restrict__ o, int n4)
{
    int i = blockIdx.x * 256 + threadIdx.x;
    if (i >= n4) return;
    float4 v = ((const float4*)in)[i];
    ((uint2*)o)[i] = make_uint2(f2h2(v.x, v.y), f2h2(v.z, v.w));
}

// ---------------- pipelined fp16 GEMM (2-stage, R12-proven) ----------------
// OMODE: 0 = fp32 C; 1 = fp16 Cf; 2 = QKV mixed (Q fp32, K|V fp16)
#define STG 32768
#define GEMM_SMEM (2 * STG)

template<int BIAS, int GELU, int OMODE>
__global__ __launch_bounds__(256, 2) void mma_gemm(
    const __half* __restrict__ Ag, const __half* __restrict__ Bg,
    const float* __restrict__ bias, float* __restrict__ C,
    __half* __restrict__ Cf, __half* __restrict__ KV,
    int M, int N, int K)
{
    extern __shared__ char smem[];
    uint32_t sb = smem_u32(smem);
    int tid = threadIdx.x, wid = tid >> 5, lane = tid & 31;
    int row0 = blockIdx.y * 128;
    int col0 = blockIdx.x * 128;
    int Am0 = (wid >> 2) * 64;
    int Bn0 = (wid & 3) * 32;

    uint32_t arow[4], brow[2];
#pragma unroll
    for (int mt = 0; mt < 4; mt++)
        arow[mt] = (uint32_t)((Am0 + mt * 16 + (lane & 15)) * 128 + (lane >> 4) * 16);
#pragma unroll
    for (int ntp = 0; ntp < 2; ntp++)
        brow[ntp] = (uint32_t)((Bn0 + ntp * 16 + (lane >> 4) * 8 + (lane & 7)) * 128
                               + ((lane >> 3) & 1) * 16);

    float d[4][4][4];
#pragma unroll
    for (int i = 0; i < 4; i++)
#pragma unroll
        for (int j = 0; j < 4; j++)
#pragma unroll
            for (int e = 0; e < 4; e++) d[i][j][e] = 0.f;

    auto load_stage = [&](int st, int kt) {
        uint32_t base = sb + st * STG;
#pragma unroll
        for (int j = 0; j < 4; j++) {
            int id = tid + 256 * j;
            int r = id >> 3, c = id & 7;
            uint32_t off = SWZ((uint32_t)(r * 128 + c * 16));
            int gr = row0 + r;
            uint32_t sz = (gr < M) ? 16u : 0u;
            int grc = (gr < M) ? gr : (M - 1);
            cpa16(base + off, Ag + (size_t)grc * K + kt + c * 8, sz);
            int gn = col0 + r;
            cpa16(base + 16384 + off, Bg + (size_t)gn * K + kt + c * 8, 16u);
        }
    };

    load_stage(0, 0);
    CP_COMMIT();

    const int nIter = K >> 6;
    for (int it = 0; it < nIter; ++it) {
        if (it + 1 < nIter) load_stage((it + 1) & 1, (it + 1) << 6);
        CP_COMMIT();
        CP_WAIT1();
        __syncthreads();

        uint32_t sA = sb + (it & 1) * STG;
        uint32_t sB = sA + 16384;
#pragma unroll
        for (int ks = 0; ks < 4; ks++) {
            uint32_t aF[4][4], bF[4][2];
#pragma unroll
            for (int mt = 0; mt < 4; mt++)
                ldm_x4(aF[mt], sA + SWZ(arow[mt] + ks * 32));
#pragma unroll
            for (int ntp = 0; ntp < 2; ntp++)
                ldm_x4(&bF[ntp * 2][0], sB + SWZ(brow[ntp] + ks * 32));
#pragma unroll
            for (int mt = 0; mt < 4; mt++)
#pragma unroll
                for (int nt = 0; nt < 4; nt++)
                    mma_f16(d[mt][nt], aF[mt], bF[nt]);
        }
        __syncthreads();
    }

#pragma unroll
    for (int nt = 0; nt < 4; nt++) {
        int c = col0 + Bn0 + nt * 8 + (lane & 3) * 2;
        float b0 = 0.f, b1 = 0.f;
        if (BIAS) { b0 = bias[c]; b1 = bias[c + 1]; }
#pragma unroll
        for (int mt = 0; mt < 4; mt++) {
            int r0 = row0 + Am0 + mt * 16 + (lane >> 2);
#pragma unroll
            for (int half = 0; half < 2; half++) {
                int r = r0 + half * 8;
                if (r < M) {
                    float v0 = d[mt][nt][half * 2 + 0] + b0;
                    float v1 = d[mt][nt][half * 2 + 1] + b1;
                    if (GELU) {
                        v0 = 0.5f * v0 * (1.f + erff(v0 * 0.70710678118654752f));
                        v1 = 0.5f * v1 * (1.f + erff(v1 * 0.70710678118654752f));
                    }
                    if (OMODE == 1) {
                        *(uint32_t*)(Cf + (size_t)r * N + c) = f2h2(v0, v1);
                    } else if (OMODE == 2) {
                        if (col0 < 256) {
                            *(float2*)(C + (size_t)r * CC + c) = make_float2(v0, v1);
                        } else {
                            *(uint32_t*)(KV + (size_t)r * 512 + (c - 256)) = f2h2(v0, v1);
                        }
                    } else {
                        *(float2*)(C + (size_t)r * N + c) = make_float2(v0, v1);
                    }
                }
            }
        }
    }
}

// ---------------- GEMM + residual + LayerNorm fused (2-stage, R12-proven) ----------------
#define LSTG 49152
#define LN_SMEM (2 * LSTG)

template<int SPLIT>
__global__ __launch_bounds__(512, 1) void mma_gemm_ln(
    const __half* __restrict__ Ag, const __half* __restrict__ Bg,
    const float* __restrict__ bias, const float* __restrict__ Res,
    const float* __restrict__ lnG, const float* __restrict__ lnB,
    float* __restrict__ Out, __half* __restrict__ Of,
    int M, int K)
{
    extern __shared__ char smem[];
    uint32_t sb = smem_u32(smem);
    int tid = threadIdx.x, wid = tid >> 5, lane = tid & 31;
    int row0 = blockIdx.y * 128;
    int wM = wid >> 2, wN = wid & 3;
    int Am0 = wM * 32;
    int Bn0 = wN * 64;

    uint32_t arow[2], brow[4];
#pragma unroll
    for (int mt = 0; mt < 2; mt++)
        arow[mt] = (uint32_t)((Am0 + mt * 16 + (lane & 15)) * 128 + (lane >> 4) * 16);
#pragma unroll
    for (int ntp = 0; ntp < 4; ntp++)
        brow[ntp] = (uint32_t)((Bn0 + ntp * 16 + (lane >> 4) * 8 + (lane & 7)) * 128
                               + ((lane >> 3) & 1) * 16);

    float d[2][8][4];
#pragma unroll
    for (int i = 0; i < 2; i++)
#pragma unroll
        for (int j = 0; j < 8; j++)
#pragma unroll
            for (int e = 0; e < 4; e++) d[i][j][e] = 0.f;

    auto load_stage = [&](int st, int kt) {
        uint32_t base = sb + st * LSTG;
#pragma unroll
        for (int j = 0; j < 2; j++) {
            int id = tid + 512 * j;
            int r = id >> 3, c = id & 7;
            uint32_t off = SWZ((uint32_t)(r * 128 + c * 16));
            int gr = row0 + r;
            uint32_t sz = (gr < M) ? 16u : 0u;
            int grc = (gr < M) ? gr : (M - 1);
            cpa16(base + off, Ag + (size_t)grc * K + kt + c * 8, sz);
        }
#pragma unroll
        for (int j = 0; j < 4; j++) {
            int id = tid + 512 * j;
            int r = id >> 3, c = id & 7;
            uint32_t off = SWZ((uint32_t)(r * 128 + c * 16));
            cpa16(base + 16384 + off, Bg + (size_t)r * K + kt + c * 8, 16u);
        }
    };

    load_stage(0, 0);
    CP_COMMIT();

    const int nIter = K >> 6;
    for (int it = 0; it < nIter; ++it) {
        if (it + 1 < nIter) load_stage((it + 1) & 1, (it + 1) << 6);
        CP_COMMIT();
        CP_WAIT1();
        __syncthreads();

        uint32_t sA = sb + (it & 1) * LSTG;
        uint32_t sB = sA + 16384;
#pragma unroll
        for (int ks = 0; ks < 4; ks++) {
            uint32_t aF[2][4], bF[8][2];
#pragma unroll
            for (int mt = 0; mt < 2; mt++)
                ldm_x4(aF[mt], sA + SWZ(arow[mt] + ks * 32));
#pragma unroll
            for (int ntp = 0; ntp < 4; ntp++)
                ldm_x4(&bF[ntp * 2][0], sB + SWZ(brow[ntp] + ks * 32));
#pragma unroll
            for (int mt = 0; mt < 2; mt++)
#pragma unroll
                for (int nt = 0; nt < 8; nt++)
                    mma_f16(d[mt][nt], aF[mt], bF[nt]);
        }
        __syncthreads();
    }

    float* part = (float*)smem;
    float psum[2][2], psq[2][2];
#pragma unroll
    for (int mt = 0; mt < 2; mt++)
#pragma unroll
    for (int half = 0; half < 2; half++) {
        int lr = Am0 + mt * 16 + (lane >> 2) + half * 8;
        int r = row0 + lr;
        float s = 0.f, q = 0.f;
#pragma unroll
        for (int nt = 0; nt < 8; nt++) {
            int c = Bn0 + nt * 8 + (lane & 3) * 2;
            float2 res = (r < M) ? *(const float2*)(Res + (size_t)r * CC + c)
                                 : make_float2(0.f, 0.f);
            float v0 = d[mt][nt][half * 2 + 0] + bias[c] + res.x;
            float v1 = d[mt][nt][half * 2 + 1] + bias[c + 1] + res.y;
            d[mt][nt][half * 2 + 0] = v0;
            d[mt][nt][half * 2 + 1] = v1;
            s += v0 + v1;
            q += v0 * v0 + v1 * v1;
        }
        s += __shfl_xor_sync(0xffffffffu, s, 1);
        q += __shfl_xor_sync(0xffffffffu, q, 1);
        s += __shfl_xor_sync(0xffffffffu, s, 2);
        q += __shfl_xor_sync(0xffffffffu, q, 2);
        psum[mt][half] = s;
        psq[mt][half] = q;
    }
    if ((lane & 3) == 0) {
#pragma unroll
        for (int mt = 0; mt < 2; mt++)
#pragma unroll
        for (int half = 0; half < 2; half++) {
            int lr = Am0 + mt * 16 + (lane >> 2) + half * 8;
            part[(lr * 4 + wN) * 2 + 0] = psum[mt][half];
            part[(lr * 4 + wN) * 2 + 1] = psq[mt][half];
        }
    }
    __syncthreads();

#pragma unroll
    for (int mt = 0; mt < 2; mt++)
#pragma unroll
    for (int half = 0; half < 2; half++) {
        int lr = Am0 + mt * 16 + (lane >> 2) + half * 8;
        int r = row0 + lr;
        if (r >= M) continue;
        float S = part[(lr * 4 + 0) * 2] + part[(lr * 4 + 1) * 2]
                + part[(lr * 4 + 2) * 2] + part[(lr * 4 + 3) * 2];
        float Q = part[(lr * 4 + 0) * 2 + 1] + part[(lr * 4 + 1) * 2 + 1]
                + part[(lr * 4 + 2) * 2 + 1] + part[(lr * 4 + 3) * 2 + 1];
        float mu = S * (1.f / 256.f);
        float var = Q * (1.f / 256.f) - mu * mu;
        float rs = rsqrtf(var + 1e-5f);
#pragma unroll
        for (int nt = 0; nt < 8; nt++) {
            int c = Bn0 + nt * 8 + (lane & 3) * 2;
            float o0 = (d[mt][nt][half * 2 + 0] - mu) * rs * lnG[c] + lnB[c];
            float o1 = (d[mt][nt][half * 2 + 1] - mu) * rs * lnG[c + 1] + lnB[c + 1];
            *(float2*)(Out + (size_t)r * CC + c) = make_float2(o0, o1);
            if (SPLIT)
                *(uint32_t*)(Of + (size_t)r * CC + c) = f2h2(o0, o1);
        }
    }
}

// ---------------- CSR sort: hist -> scan -> scatter ----------------
__global__ void zero_cnt() {
    int i = blockIdx.x * 256 + threadIdx.x;
    if (i < NN) g_cnt[i] = 0;
}
__global__ void hist_kernel(const int* __restrict__ ei) {
    int e = blockIdx.x * 256 + threadIdx.x;
    if (e < EE) atomicAdd(&g_cnt[ei[EE + e]], 1);
}
__global__ __launch_bounds__(1024) void scan_kernel() {
    __shared__ int part[1024];
    const int CH = 49;
    int t = threadIdx.x;
    int base = t * CH;
    int s = 0;
    for (int j = 0; j < CH; j++) {
        int i = base + j;
        if (i < NN) s += g_cnt[i];
    }
    part[t] = s;
    __syncthreads();
    for (int off = 1; off < 1024; off <<= 1) {
        int v = (t >= off) ? part[t - off] : 0;
        __syncthreads();
        part[t] += v;
        __syncthreads();
    }
    int run = (t == 0) ? 0 : part[t - 1];
    for (int j = 0; j < CH; j++) {
        int i = base + j;
        if (i < NN) {
            g_ofs[i] = run;
            g_cur[i] = run;
            run += g_cnt[i];
        }
    }
}
__global__ void scatter_kernel(const int* __restrict__ ei) {
    int e = blockIdx.x * 256 + threadIdx.x;
    if (e >= EE) return;
    int dst = ei[EE + e];
    int pos = atomicAdd(&g_cur[dst], 1);
    g_ss[pos] = ei[e];
}

// ---------------- fused per-dst attention: single-pass online softmax, fp16 K/V ----------------
__global__ __launch_bounds__(256) void attn_kernel(
    const float* __restrict__ Qp, const __half* __restrict__ KVp,
    __half* __restrict__ of)
{
    int tid = threadIdx.x;
    int w = tid >> 5, lane = tid & 31;
    int h = lane >> 2, sub = lane & 3;
    int dst = blockIdx.x * 8 + w;

    const float* qp = Qp + (size_t)dst * CC + h * DD + sub * 8;
    float4 q0 = __ldg((const float4*)qp);
    float4 q1 = __ldg((const float4*)qp + 1);
    const float* qf0 = &q0.x;
    const float* qf1 = &q1.x;
    int beg = g_ofs[dst], cnt = g_cnt[dst];

    float m = 0.f, sum = 0.f;
    float a[8];
#pragma unroll
    for (int e = 0; e < 8; e++) a[e] = 0.f;

    int i = 0;
    for (; i + 1 < cnt; i += 2) {
        int s0 = g_ss[beg + i], s1 = g_ss[beg + i + 1];
        const __half* b0p = KVp + (size_t)s0 * 512 + h * DD + sub * 8;
        const __half* b1p = KVp + (size_t)s1 * 512 + h * DD + sub * 8;
        uint4 k0r = __ldg((const uint4*)b0p);
        uint4 k1r = __ldg((const uint4*)b1p);
        uint4 v0r = __ldg((const uint4*)(b0p + 256));
        uint4 v1r = __ldg((const uint4*)(b1p + 256));
        float kf0[8], kf1[8], vf0[8], vf1[8];
        h8_to_f(k0r, kf0); h8_to_f(k1r, kf1);
        h8_to_f(v0r, vf0); h8_to_f(v1r, vf1);
        float d0 = 0.f, d1 = 0.f;
#pragma unroll
        for (int e = 0; e < 4; e++) {
            d0 += qf0[e] * kf0[e] + qf1[e] * kf0[4 + e];
            d1 += qf0[e] * kf1[e] + qf1[e] * kf1[4 + e];
        }
        d0 += __shfl_xor_sync(0xffffffffu, d0, 1);
        d1 += __shfl_xor_sync(0xffffffffu, d1, 1);
        d0 += __shfl_xor_sync(0xffffffffu, d0, 2);
        d1 += __shfl_xor_sync(0xffffffffu, d1, 2);
        float sa = d0 * SCALE, sb2 = d1 * SCALE;
        float nm = fmaxf(m, fmaxf(sa, sb2));
        float f  = __expf(m - nm);
        float wa = __expf(sa - nm), wb = __expf(sb2 - nm);
        m = nm;
        sum = sum * f + wa + wb;
#pragma unroll
        for (int e = 0; e < 8; e++)
            a[e] = a[e] * f + wa * vf0[e] + wb * vf1[e];
    }
    if (i < cnt) {
        int s0 = g_ss[beg + i];
        const __half* b0p = KVp + (size_t)s0 * 512 + h * DD + sub * 8;
        uint4 k0r = __ldg((const uint4*)b0p);
        uint4 v0r = __ldg((const uint4*)(b0p + 256));
        float kf0[8], vf0[8];
        h8_to_f(k0r, kf0);
        h8_to_f(v0r, vf0);
        float d0 = 0.f;
#pragma unroll
        for (int e = 0; e < 4; e++)
            d0 += qf0[e] * kf0[e] + qf1[e] * kf0[4 + e];
        d0 += __shfl_xor_sync(0xffffffffu, d0, 1);
        d0 += __shfl_xor_sync(0xffffffffu, d0, 2);
        float sa = d0 * SCALE;
        float nm = fmaxf(m, sa);
        float f  = __expf(m - nm);
        float wa = __expf(sa - nm);
        m = nm;
        sum = sum * f + wa;
#pragma unroll
        for (int e = 0; e < 8; e++)
            a[e] = a[e] * f + wa * vf0[e];
    }

    float inv = 1.f / (sum + 1e-8f);
    uint4 o;
    o.x = f2h2(a[0] * inv, a[1] * inv);
    o.y = f2h2(a[2] * inv, a[3] * inv);
    o.z = f2h2(a[4] * inv, a[5] * inv);
    o.w = f2h2(a[6] * inv, a[7] * inv);
    *(uint4*)(of + (size_t)dst * CC + h * DD + sub * 8) = o;
}

// ---------------- launch ----------------
extern "C" void kernel_launch(void* const* d_in, const int* in_sizes, int n_in,
                              void* d_out, int out_size)
{
    const float* x      = (const float*)d_in[0];
    const int*   ei     = (const int*)d_in[1];
    const float* Wq     = (const float*)d_in[3];
    const float* Wk     = (const float*)d_in[4];
    const float* Wv     = (const float*)d_in[5];
    const float* Wo_w   = (const float*)d_in[6];
    const float* Wo_b   = (const float*)d_in[7];
    const float* ln1_g  = (const float*)d_in[8];
    const float* ln1_b  = (const float*)d_in[9];
    const float* ln2_g  = (const float*)d_in[10];
    const float* ln2_b  = (const float*)d_in[11];
    const float* ffn_w1 = (const float*)d_in[12];
    const float* ffn_b1 = (const float*)d_in[13];
    const float* ffn_w2 = (const float*)d_in[14];
    const float* ffn_b2 = (const float*)d_in[15];
    float* out = (float*)d_out;

    float *pQ, *pH1;
    __half *pKV, *pXf, *pAf, *pHf, *pTf, *pW;
    cudaGetSymbolAddress((void**)&pQ,   g_Q);
    cudaGetSymbolAddress((void**)&pKV,  g_KV);
    cudaGetSymbolAddress((void**)&pH1,  g_h1);
    cudaGetSymbolAddress((void**)&pXf,  g_Xf);
    cudaGetSymbolAddress((void**)&pAf,  g_Af);
    cudaGetSymbolAddress((void**)&pHf,  g_Hf);
    cudaGetSymbolAddress((void**)&pTf,  g_Tf);
    cudaGetSymbolAddress((void**)&pW,   g_W);

    cudaFuncSetAttribute(mma_gemm<0, 0, 2>, cudaFuncAttributeMaxDynamicSharedMemorySize, GEMM_SMEM);
    cudaFuncSetAttribute(mma_gemm<1, 1, 1>, cudaFuncAttributeMaxDynamicSharedMemorySize, GEMM_SMEM);
    cudaFuncSetAttribute(mma_gemm_ln<0>, cudaFuncAttributeMaxDynamicSharedMemorySize, LN_SMEM);
    cudaFuncSetAttribute(mma_gemm_ln<1>, cudaFuncAttributeMaxDynamicSharedMemorySize, LN_SMEM);

    // lazy host-side resources (created on the first, non-captured call; reused after)
    static cudaStream_t s2 = nullptr, s3 = nullptr;
    static cudaEvent_t evRoot = nullptr, evSort = nullptr, evPrep = nullptr;
    if (s2 == nullptr) {
        cudaStreamCreateWithFlags(&s2, cudaStreamNonBlocking);
        cudaStreamCreateWithFlags(&s3, cudaStreamNonBlocking);
        cudaEventCreateWithFlags(&evRoot, cudaEventDisableTiming);
        cudaEventCreateWithFlags(&evSort, cudaEventDisableTiming);
        cudaEventCreateWithFlags(&evPrep, cudaEventDisableTiming);
    }

    const int MT = (NN + 127) / 128;     // 391

    cudaEventRecord(evRoot, 0);

    // ---- fork A: CSR sort chain on s2 ----
    cudaStreamWaitEvent(s2, evRoot, 0);
    zero_cnt<<<(NN + 255) / 256, 256, 0, s2>>>();
    hist_kernel<<<(EE + 255) / 256, 256, 0, s2>>>(ei);
    scan_kernel<<<1, 1024, 0, s2>>>();
    scatter_kernel<<<(EE + 255) / 256, 256, 0, s2>>>(ei);
    cudaEventRecord(evSort, s2);

    // ---- fork B: weight prep on s3 (qkv slice first) ----
    cudaStreamWaitEvent(s3, evRoot, 0);
    prep_qkv<<<(W_WO + 255) / 256, 256, 0, s3>>>(Wq, Wk, Wv);
    cudaEventRecord(evPrep, s3);
    prep_rest<<<((W_TOT - W_WO) + 255) / 256, 256, 0, s3>>>(Wo_w, ffn_w1, ffn_w2);

    // ---- main: activation convert (concurrent with both forks) ----
    conv_f16<<<(NN * CC / 4 + 255) / 256, 256>>>(x, pXf, NN * CC / 4);

    // QKV needs conv (main) + qkv weights (s3)
    cudaStreamWaitEvent(0, evPrep, 0);
    mma_gemm<0, 0, 2><<<dim3(6, MT), 256, GEMM_SMEM>>>(
        pXf, pW + W_QKV, nullptr, pQ, nullptr, pKV, NN, 768, CC);

    // ---- join: attention needs QKV + sorted CSR ----
    cudaStreamWaitEvent(0, evSort, 0);
    attn_kernel<<<NN / 8, 256>>>(pQ, pKV, pAf);

    // Wo + residual(x) + LN1  (needs prep_rest; s3 joined via stream-order below)
    cudaStreamWaitEvent(0, evSort, 0);   // no-op, keeps graph simple
    {
        // join s3 fully before first use of Wo/F1/F2 weights
        static cudaEvent_t evPrep2 = nullptr;
        if (evPrep2 == nullptr) cudaEventCreateWithFlags(&evPrep2, cudaEventDisableTiming);
        cudaEventRecord(evPrep2, s3);
        cudaStreamWaitEvent(0, evPrep2, 0);
    }
    mma_gemm_ln<1><<<dim3(1, MT), 512, LN_SMEM>>>(
        pAf, pW + W_WO, Wo_b, x, ln1_g, ln1_b, pH1, pHf, NN, CC);

    // FFN1 + GELU -> hidden fp16
    mma_gemm<1, 1, 1><<<dim3(4, MT), 256, GEMM_SMEM>>>(
        pHf, pW + W_F1, ffn_b1, nullptr, pTf, nullptr, NN, FF, CC);

    // FFN2 + residual(h1) + LN2 -> out
    mma_gemm_ln<0><<<dim3(1, MT), 512, LN_SMEM>>>(
        pTf, pW + W_F2, ffn_b2, pH1, ln2_g, ln2_b, out, nullptr, NN, FF);
}

// round 15
// speedup vs baseline: 1.0059x; 1.0059x over previous
#include <cuda_runtime.h>
#include <cuda_fp16.h>
#include <cstdint>

#define NN 50000
#define EE 800000
#define CC 256
#define HH 8
#define DD 32
#define FF 512
#define SCALE 0.17677669529663689f

#define W_QKV 0
#define W_WO  196608
#define W_F1  262144
#define W_F2  393216
#define W_TOT 524288

// ---------------- scratch ----------------
__device__ float g_Q[(size_t)NN * CC];            // Q fp32
__device__ __half g_KV[(size_t)NN * 512];         // K|V fp16 packed per node
__device__ float g_h1[(size_t)NN * CC];           // ln1 out fp32
__device__ __half g_Xf[(size_t)NN * CC];          // x fp16
__device__ __half g_Af[(size_t)NN * CC];          // attn agg fp16
__device__ __half g_Hf[(size_t)NN * CC];          // h1 fp16
__device__ __half g_Tf[(size_t)NN * FF];          // ffn hidden fp16
__device__ __half g_W[W_TOT];                     // weights fp16, k-major
__device__ int g_cnt[NN], g_ofs[NN], g_cur[NN];
__device__ int g_ss[EE];                          // src sorted by dst

// ---------------- helpers ----------------
__device__ __forceinline__ uint32_t smem_u32(const void* p) {
    uint32_t a;
    asm("{ .reg .u64 t; cvta.to.shared.u64 t, %1; cvt.u32.u64 %0, t; }" : "=r"(a) : "l"(p));
    return a;
}
#define SWZ(off) ((off) ^ (((off) >> 3) & 0x70))

__device__ __forceinline__ void ldm_x4(uint32_t* r, uint32_t addr) {
    asm volatile("ldmatrix.sync.aligned.m8n8.x4.shared.b16 {%0,%1,%2,%3}, [%4];"
        : "=r"(r[0]), "=r"(r[1]), "=r"(r[2]), "=r"(r[3]) : "r"(addr));
}
__device__ __forceinline__ void mma_f16(float* d, const uint32_t* a, const uint32_t* b) {
    asm volatile("mma.sync.aligned.m16n8k16.row.col.f32.f16.f16.f32 "
        "{%0,%1,%2,%3}, {%4,%5,%6,%7}, {%8,%9}, {%0,%1,%2,%3};"
        : "+f"(d[0]), "+f"(d[1]), "+f"(d[2]), "+f"(d[3])
        : "r"(a[0]), "r"(a[1]), "r"(a[2]), "r"(a[3]), "r"(b[0]), "r"(b[1]));
}
__device__ __forceinline__ uint32_t f2h2(float x, float y) {
    __half2 h = __float22half2_rn(make_float2(x, y));
    return *(uint32_t*)&h;
}
__device__ __forceinline__ void cpa16(uint32_t dst, const void* src, uint32_t sz) {
    asm volatile("cp.async.cg.shared.global [%0], [%1], 16, %2;"
        :: "r"(dst), "l"(src), "r"(sz) : "memory");
}
#define CP_COMMIT() asm volatile("cp.async.commit_group;" ::: "memory")
#define CP_WAIT1()  asm volatile("cp.async.wait_group 1;" ::: "memory")

// unpack 8 fp16 (uint4) -> 8 floats
__device__ __forceinline__ void h8_to_f(const uint4& r, float* f) {
    float2 t;
    t = __half22float2(*(const __half2*)&r.x); f[0] = t.x; f[1] = t.y;
    t = __half22float2(*(const __half2*)&r.y); f[2] = t.x; f[3] = t.y;
    t = __half22float2(*(const __half2*)&r.z); f[4] = t.x; f[5] = t.y;
    t = __half22float2(*(const __half2*)&r.w); f[6] = t.x; f[7] = t.y;
}

// ---------------- weight prep: transpose to k-major fp16 ----------------
__global__ void prep_weights(const float* __restrict__ Wq, const float* __restrict__ Wk,
                             const float* __restrict__ Wv, const float* __restrict__ Wo,
                             const float* __restrict__ F1, const float* __restrict__ F2)
{
    int idx = blockIdx.x * 256 + threadIdx.x;
    if (idx >= W_TOT) return;
    float w;
    if (idx < W_WO) {
        int n = idx >> 8, k = idx & 255;
        if (n < 256)      w = Wq[k * 256 + n];
        else if (n < 512) w = Wk[k * 256 + (n - 256)];
        else              w = Wv[k * 256 + (n - 512)];
    } else if (idx < W_F1) {
        int l = idx - W_WO;
        int n = l >> 8, k = l & 255;
        w = Wo[k * 256 + n];
    } else if (idx < W_F2) {
        int l = idx - W_F1;
        int n = l >> 8, k = l & 255;
        w = F1[k * 512 + n];
    } else {
        int l = idx - W_F2;
        int n = l >> 9, k = l & 511;
        w = F2[k * 256 + n];
    }
    g_W[idx] = __float2half(w);
}

// ---------------- fp32 -> fp16 convert (vectorized) ----------------
__global__ void conv_f16(const float* __restrict__ in, __half* __restrict__ o, int n4)
{
    int i = blockIdx.x * 256 + threadIdx.x;
    if (i >= n4) return;
    float4 v = ((const float4*)in)[i];
    ((uint2*)o)[i] = make_uint2(f2h2(v.x, v.y), f2h2(v.z, v.w));
}

// ---------------- pipelined fp16 GEMM (2-stage, R12-proven) ----------------
// OMODE: 0 = fp32 C; 1 = fp16 Cf; 2 = QKV mixed (Q fp32, K|V fp16)
#define STG 32768
#define GEMM_SMEM (2 * STG)

template<int BIAS, int GELU, int OMODE>
__global__ __launch_bounds__(256, 2) void mma_gemm(
    const __half* __restrict__ Ag, const __half* __restrict__ Bg,
    const float* __restrict__ bias, float* __restrict__ C,
    __half* __restrict__ Cf, __half* __restrict__ KV,
    int M, int N, int K)
{
    extern __shared__ char smem[];
    uint32_t sb = smem_u32(smem);
    int tid = threadIdx.x, wid = tid >> 5, lane = tid & 31;
    int row0 = blockIdx.y * 128;
    int col0 = blockIdx.x * 128;
    int Am0 = (wid >> 2) * 64;
    int Bn0 = (wid & 3) * 32;

    uint32_t arow[4], brow[2];
#pragma unroll
    for (int mt = 0; mt < 4; mt++)
        arow[mt] = (uint32_t)((Am0 + mt * 16 + (lane & 15)) * 128 + (lane >> 4) * 16);
#pragma unroll
    for (int ntp = 0; ntp < 2; ntp++)
        brow[ntp] = (uint32_t)((Bn0 + ntp * 16 + (lane >> 4) * 8 + (lane & 7)) * 128
                               + ((lane >> 3) & 1) * 16);

    float d[4][4][4];
#pragma unroll
    for (int i = 0; i < 4; i++)
#pragma unroll
        for (int j = 0; j < 4; j++)
#pragma unroll
            for (int e = 0; e < 4; e++) d[i][j][e] = 0.f;

    auto load_stage = [&](int st, int kt) {
        uint32_t base = sb + st * STG;
#pragma unroll
        for (int j = 0; j < 4; j++) {
            int id = tid + 256 * j;
            int r = id >> 3, c = id & 7;
            uint32_t off = SWZ((uint32_t)(r * 128 + c * 16));
            int gr = row0 + r;
            uint32_t sz = (gr < M) ? 16u : 0u;
            int grc = (gr < M) ? gr : (M - 1);
            cpa16(base + off, Ag + (size_t)grc * K + kt + c * 8, sz);
            int gn = col0 + r;
            cpa16(base + 16384 + off, Bg + (size_t)gn * K + kt + c * 8, 16u);
        }
    };

    load_stage(0, 0);
    CP_COMMIT();

    const int nIter = K >> 6;
    for (int it = 0; it < nIter; ++it) {
        if (it + 1 < nIter) load_stage((it + 1) & 1, (it + 1) << 6);
        CP_COMMIT();
        CP_WAIT1();
        __syncthreads();

        uint32_t sA = sb + (it & 1) * STG;
        uint32_t sB = sA + 16384;
#pragma unroll
        for (int ks = 0; ks < 4; ks++) {
            uint32_t aF[4][4], bF[4][2];
#pragma unroll
            for (int mt = 0; mt < 4; mt++)
                ldm_x4(aF[mt], sA + SWZ(arow[mt] + ks * 32));
#pragma unroll
            for (int ntp = 0; ntp < 2; ntp++)
                ldm_x4(&bF[ntp * 2][0], sB + SWZ(brow[ntp] + ks * 32));
#pragma unroll
            for (int mt = 0; mt < 4; mt++)
#pragma unroll
                for (int nt = 0; nt < 4; nt++)
                    mma_f16(d[mt][nt], aF[mt], bF[nt]);
        }
        __syncthreads();
    }

#pragma unroll
    for (int nt = 0; nt < 4; nt++) {
        int c = col0 + Bn0 + nt * 8 + (lane & 3) * 2;
        float b0 = 0.f, b1 = 0.f;
        if (BIAS) { b0 = bias[c]; b1 = bias[c + 1]; }
#pragma unroll
        for (int mt = 0; mt < 4; mt++) {
            int r0 = row0 + Am0 + mt * 16 + (lane >> 2);
#pragma unroll
            for (int half = 0; half < 2; half++) {
                int r = r0 + half * 8;
                if (r < M) {
                    float v0 = d[mt][nt][half * 2 + 0] + b0;
                    float v1 = d[mt][nt][half * 2 + 1] + b1;
                    if (GELU) {
                        v0 = 0.5f * v0 * (1.f + erff(v0 * 0.70710678118654752f));
                        v1 = 0.5f * v1 * (1.f + erff(v1 * 0.70710678118654752f));
                    }
                    if (OMODE == 1) {
                        *(uint32_t*)(Cf + (size_t)r * N + c) = f2h2(v0, v1);
                    } else if (OMODE == 2) {
                        if (col0 < 256) {
                            *(float2*)(C + (size_t)r * CC + c) = make_float2(v0, v1);
                        } else {
                            *(uint32_t*)(KV + (size_t)r * 512 + (c - 256)) = f2h2(v0, v1);
                        }
                    } else {
                        *(float2*)(C + (size_t)r * N + c) = make_float2(v0, v1);
                    }
                }
            }
        }
    }
}

// ---------------- GEMM + residual + LayerNorm fused (2-stage, R12-proven) ----------------
#define LSTG 49152
#define LN_SMEM (2 * LSTG)

template<int SPLIT>
__global__ __launch_bounds__(512, 1) void mma_gemm_ln(
    const __half* __restrict__ Ag, const __half* __restrict__ Bg,
    const float* __restrict__ bias, const float* __restrict__ Res,
    const float* __restrict__ lnG, const float* __restrict__ lnB,
    float* __restrict__ Out, __half* __restrict__ Of,
    int M, int K)
{
    extern __shared__ char smem[];
    uint32_t sb = smem_u32(smem);
    int tid = threadIdx.x, wid = tid >> 5, lane = tid & 31;
    int row0 = blockIdx.y * 128;
    int wM = wid >> 2, wN = wid & 3;
    int Am0 = wM * 32;
    int Bn0 = wN * 64;

    uint32_t arow[2], brow[4];
#pragma unroll
    for (int mt = 0; mt < 2; mt++)
        arow[mt] = (uint32_t)((Am0 + mt * 16 + (lane & 15)) * 128 + (lane >> 4) * 16);
#pragma unroll
    for (int ntp = 0; ntp < 4; ntp++)
        brow[ntp] = (uint32_t)((Bn0 + ntp * 16 + (lane >> 4) * 8 + (lane & 7)) * 128
                               + ((lane >> 3) & 1) * 16);

    float d[2][8][4];
#pragma unroll
    for (int i = 0; i < 2; i++)
#pragma unroll
        for (int j = 0; j < 8; j++)
#pragma unroll
            for (int e = 0; e < 4; e++) d[i][j][e] = 0.f;

    auto load_stage = [&](int st, int kt) {
        uint32_t base = sb + st * LSTG;
#pragma unroll
        for (int j = 0; j < 2; j++) {
            int id = tid + 512 * j;
            int r = id >> 3, c = id & 7;
            uint32_t off = SWZ((uint32_t)(r * 128 + c * 16));
            int gr = row0 + r;
            uint32_t sz = (gr < M) ? 16u : 0u;
            int grc = (gr < M) ? gr : (M - 1);
            cpa16(base + off, Ag + (size_t)grc * K + kt + c * 8, sz);
        }
#pragma unroll
        for (int j = 0; j < 4; j++) {
            int id = tid + 512 * j;
            int r = id >> 3, c = id & 7;
            uint32_t off = SWZ((uint32_t)(r * 128 + c * 16));
            cpa16(base + 16384 + off, Bg + (size_t)r * K + kt + c * 8, 16u);
        }
    };

    load_stage(0, 0);
    CP_COMMIT();

    const int nIter = K >> 6;
    for (int it = 0; it < nIter; ++it) {
        if (it + 1 < nIter) load_stage((it + 1) & 1, (it + 1) << 6);
        CP_COMMIT();
        CP_WAIT1();
        __syncthreads();

        uint32_t sA = sb + (it & 1) * LSTG;
        uint32_t sB = sA + 16384;
#pragma unroll
        for (int ks = 0; ks < 4; ks++) {
            uint32_t aF[2][4], bF[8][2];
#pragma unroll
            for (int mt = 0; mt < 2; mt++)
                ldm_x4(aF[mt], sA + SWZ(arow[mt] + ks * 32));
#pragma unroll
            for (int ntp = 0; ntp < 4; ntp++)
                ldm_x4(&bF[ntp * 2][0], sB + SWZ(brow[ntp] + ks * 32));
#pragma unroll
            for (int mt = 0; mt < 2; mt++)
#pragma unroll
                for (int nt = 0; nt < 8; nt++)
                    mma_f16(d[mt][nt], aF[mt], bF[nt]);
        }
        __syncthreads();
    }

    float* part = (float*)smem;
    float psum[2][2], psq[2][2];
#pragma unroll
    for (int mt = 0; mt < 2; mt++)
#pragma unroll
    for (int half = 0; half < 2; half++) {
        int lr = Am0 + mt * 16 + (lane >> 2) + half * 8;
        int r = row0 + lr;
        float s = 0.f, q = 0.f;
#pragma unroll
        for (int nt = 0; nt < 8; nt++) {
            int c = Bn0 + nt * 8 + (lane & 3) * 2;
            float2 res = (r < M) ? *(const float2*)(Res + (size_t)r * CC + c)
                                 : make_float2(0.f, 0.f);
            float v0 = d[mt][nt][half * 2 + 0] + bias[c] + res.x;
            float v1 = d[mt][nt][half * 2 + 1] + bias[c + 1] + res.y;
            d[mt][nt][half * 2 + 0] = v0;
            d[mt][nt][half * 2 + 1] = v1;
            s += v0 + v1;
            q += v0 * v0 + v1 * v1;
        }
        s += __shfl_xor_sync(0xffffffffu, s, 1);
        q += __shfl_xor_sync(0xffffffffu, q, 1);
        s += __shfl_xor_sync(0xffffffffu, s, 2);
        q += __shfl_xor_sync(0xffffffffu, q, 2);
        psum[mt][half] = s;
        psq[mt][half] = q;
    }
    if ((lane & 3) == 0) {
#pragma unroll
        for (int mt = 0; mt < 2; mt++)
#pragma unroll
        for (int half = 0; half < 2; half++) {
            int lr = Am0 + mt * 16 + (lane >> 2) + half * 8;
            part[(lr * 4 + wN) * 2 + 0] = psum[mt][half];
            part[(lr * 4 + wN) * 2 + 1] = psq[mt][half];
        }
    }
    __syncthreads();

#pragma unroll
    for (int mt = 0; mt < 2; mt++)
#pragma unroll
    for (int half = 0; half < 2; half++) {
        int lr = Am0 + mt * 16 + (lane >> 2) + half * 8;
        int r = row0 + lr;
        if (r >= M) continue;
        float S = part[(lr * 4 + 0) * 2] + part[(lr * 4 + 1) * 2]
                + part[(lr * 4 + 2) * 2] + part[(lr * 4 + 3) * 2];
        float Q = part[(lr * 4 + 0) * 2 + 1] + part[(lr * 4 + 1) * 2 + 1]
                + part[(lr * 4 + 2) * 2 + 1] + part[(lr * 4 + 3) * 2 + 1];
        float mu = S * (1.f / 256.f);
        float var = Q * (1.f / 256.f) - mu * mu;
        float rs = rsqrtf(var + 1e-5f);
#pragma unroll
        for (int nt = 0; nt < 8; nt++) {
            int c = Bn0 + nt * 8 + (lane & 3) * 2;
            float o0 = (d[mt][nt][half * 2 + 0] - mu) * rs * lnG[c] + lnB[c];
            float o1 = (d[mt][nt][half * 2 + 1] - mu) * rs * lnG[c + 1] + lnB[c + 1];
            *(float2*)(Out + (size_t)r * CC + c) = make_float2(o0, o1);
            if (SPLIT)
                *(uint32_t*)(Of + (size_t)r * CC + c) = f2h2(o0, o1);
        }
    }
}

// ---------------- CSR sort: hist -> scan -> scatter ----------------
__global__ void zero_cnt() {
    int i = blockIdx.x * 256 + threadIdx.x;
    if (i < NN) g_cnt[i] = 0;
}
__global__ void hist_kernel(const int* __restrict__ ei) {
    int e = blockIdx.x * 256 + threadIdx.x;
    if (e < EE) atomicAdd(&g_cnt[ei[EE + e]], 1);
}
__global__ __launch_bounds__(1024) void scan_kernel() {
    __shared__ int part[1024];
    const int CH = 49;
    int t = threadIdx.x;
    int base = t * CH;
    int s = 0;
    for (int j = 0; j < CH; j++) {
        int i = base + j;
        if (i < NN) s += g_cnt[i];
    }
    part[t] = s;
    __syncthreads();
    for (int off = 1; off < 1024; off <<= 1) {
        int v = (t >= off) ? part[t - off] : 0;
        __syncthreads();
        part[t] += v;
        __syncthreads();
    }
    int run = (t == 0) ? 0 : part[t - 1];
    for (int j = 0; j < CH; j++) {
        int i = base + j;
        if (i < NN) {
            g_ofs[i] = run;
            g_cur[i] = run;
            run += g_cnt[i];
        }
    }
}
__global__ void scatter_kernel(const int* __restrict__ ei) {
    int e = blockIdx.x * 256 + threadIdx.x;
    if (e >= EE) return;
    int dst = ei[EE + e];
    int pos = atomicAdd(&g_cur[dst], 1);
    g_ss[pos] = ei[e];
}

// ---------------- fused per-dst attention: online softmax, 4-wide unrolled ----------------
__global__ __launch_bounds__(256) void attn_kernel(__half* __restrict__ of)
{
    int tid = threadIdx.x;
    int w = tid >> 5, lane = tid & 31;
    int h = lane >> 2, sub = lane & 3;
    int dst = blockIdx.x * 8 + w;

    const float* qp = g_Q + (size_t)dst * CC + h * DD + sub * 8;
    float4 q0 = ((const float4*)qp)[0], q1 = ((const float4*)qp)[1];
    const float* qf0 = &q0.x;
    const float* qf1 = &q1.x;
    int beg = g_ofs[dst], cnt = g_cnt[dst];

    float m = 0.f, sum = 0.f;
    float a[8];
#pragma unroll
    for (int e = 0; e < 8; e++) a[e] = 0.f;

    int i = 0;
    // ---- 4-wide: 16 independent LDG.128 in flight ----
    for (; i + 3 < cnt; i += 4) {
        int s0 = g_ss[beg + i],     s1 = g_ss[beg + i + 1];
        int s2 = g_ss[beg + i + 2], s3 = g_ss[beg + i + 3];
        const __half* p0 = g_KV + (size_t)s0 * 512 + h * DD + sub * 8;
        const __half* p1 = g_KV + (size_t)s1 * 512 + h * DD + sub * 8;
        const __half* p2 = g_KV + (size_t)s2 * 512 + h * DD + sub * 8;
        const __half* p3 = g_KV + (size_t)s3 * 512 + h * DD + sub * 8;
        uint4 kr0 = *(const uint4*)p0;
        uint4 kr1 = *(const uint4*)p1;
        uint4 kr2 = *(const uint4*)p2;
        uint4 kr3 = *(const uint4*)p3;
        uint4 vr0 = *(const uint4*)(p0 + 256);
        uint4 vr1 = *(const uint4*)(p1 + 256);
        uint4 vr2 = *(const uint4*)(p2 + 256);
        uint4 vr3 = *(const uint4*)(p3 + 256);
        float kf0[8], kf1[8], kf2[8], kf3[8];
        float vf0[8], vf1[8], vf2[8], vf3[8];
        h8_to_f(kr0, kf0); h8_to_f(kr1, kf1); h8_to_f(kr2, kf2); h8_to_f(kr3, kf3);
        h8_to_f(vr0, vf0); h8_to_f(vr1, vf1); h8_to_f(vr2, vf2); h8_to_f(vr3, vf3);
        float d0 = 0.f, d1 = 0.f, d2 = 0.f, d3 = 0.f;
#pragma unroll
        for (int e = 0; e < 4; e++) {
            d0 += qf0[e] * kf0[e] + qf1[e] * kf0[4 + e];
            d1 += qf0[e] * kf1[e] + qf1[e] * kf1[4 + e];
            d2 += qf0[e] * kf2[e] + qf1[e] * kf2[4 + e];
            d3 += qf0[e] * kf3[e] + qf1[e] * kf3[4 + e];
        }
        d0 += __shfl_xor_sync(0xffffffffu, d0, 1);
        d1 += __shfl_xor_sync(0xffffffffu, d1, 1);
        d2 += __shfl_xor_sync(0xffffffffu, d2, 1);
        d3 += __shfl_xor_sync(0xffffffffu, d3, 1);
        d0 += __shfl_xor_sync(0xffffffffu, d0, 2);
        d1 += __shfl_xor_sync(0xffffffffu, d1, 2);
        d2 += __shfl_xor_sync(0xffffffffu, d2, 2);
        d3 += __shfl_xor_sync(0xffffffffu, d3, 2);
        float sa = d0 * SCALE, sb = d1 * SCALE, sc = d2 * SCALE, sd = d3 * SCALE;
        float nm = fmaxf(fmaxf(m, fmaxf(sa, sb)), fmaxf(sc, sd));
        float f  = __expf(m - nm);
        float wa = __expf(sa - nm), wb = __expf(sb - nm);
        float wc = __expf(sc - nm), wd = __expf(sd - nm);
        m = nm;
        sum = sum * f + (wa + wb) + (wc + wd);
#pragma unroll
        for (int e = 0; e < 8; e++)
            a[e] = a[e] * f + (wa * vf0[e] + wb * vf1[e]) + (wc * vf2[e] + wd * vf3[e]);
    }
    // ---- 2-wide tail ----
    for (; i + 1 < cnt; i += 2) {
        int s0 = g_ss[beg + i], s1 = g_ss[beg + i + 1];
        const __half* p0 = g_KV + (size_t)s0 * 512 + h * DD + sub * 8;
        const __half* p1 = g_KV + (size_t)s1 * 512 + h * DD + sub * 8;
        uint4 kr0 = *(const uint4*)p0;
        uint4 kr1 = *(const uint4*)p1;
        uint4 vr0 = *(const uint4*)(p0 + 256);
        uint4 vr1 = *(const uint4*)(p1 + 256);
        float kf0[8], kf1[8], vf0[8], vf1[8];
        h8_to_f(kr0, kf0); h8_to_f(kr1, kf1);
        h8_to_f(vr0, vf0); h8_to_f(vr1, vf1);
        float d0 = 0.f, d1 = 0.f;
#pragma unroll
        for (int e = 0; e < 4; e++) {
            d0 += qf0[e] * kf0[e] + qf1[e] * kf0[4 + e];
            d1 += qf0[e] * kf1[e] + qf1[e] * kf1[4 + e];
        }
        d0 += __shfl_xor_sync(0xffffffffu, d0, 1);
        d1 += __shfl_xor_sync(0xffffffffu, d1, 1);
        d0 += __shfl_xor_sync(0xffffffffu, d0, 2);
        d1 += __shfl_xor_sync(0xffffffffu, d1, 2);
        float sa = d0 * SCALE, sb = d1 * SCALE;
        float nm = fmaxf(m, fmaxf(sa, sb));
        float f  = __expf(m - nm);
        float wa = __expf(sa - nm), wb = __expf(sb - nm);
        m = nm;
        sum = sum * f + wa + wb;
#pragma unroll
        for (int e = 0; e < 8; e++)
            a[e] = a[e] * f + wa * vf0[e] + wb * vf1[e];
    }
    // ---- 1-wide tail ----
    if (i < cnt) {
        int s0 = g_ss[beg + i];
        const __half* p0 = g_KV + (size_t)s0 * 512 + h * DD + sub * 8;
        uint4 kr0 = *(const uint4*)p0;
        uint4 vr0 = *(const uint4*)(p0 + 256);
        float kf0[8], vf0[8];
        h8_to_f(kr0, kf0);
        h8_to_f(vr0, vf0);
        float d0 = 0.f;
#pragma unroll
        for (int e = 0; e < 4; e++)
            d0 += qf0[e] * kf0[e] + qf1[e] * kf0[4 + e];
        d0 += __shfl_xor_sync(0xffffffffu, d0, 1);
        d0 += __shfl_xor_sync(0xffffffffu, d0, 2);
        float sa = d0 * SCALE;
        float nm = fmaxf(m, sa);
        float f  = __expf(m - nm);
        float wa = __expf(sa - nm);
        m = nm;
        sum = sum * f + wa;
#pragma unroll
        for (int e = 0; e < 8; e++)
            a[e] = a[e] * f + wa * vf0[e];
    }

    float inv = 1.f / (sum + 1e-8f);
    uint4 o;
    o.x = f2h2(a[0] * inv, a[1] * inv);
    o.y = f2h2(a[2] * inv, a[3] * inv);
    o.z = f2h2(a[4] * inv, a[5] * inv);
    o.w = f2h2(a[6] * inv, a[7] * inv);
    *(uint4*)(of + (size_t)dst * CC + h * DD + sub * 8) = o;
}

// ---------------- launch (R12 topology) ----------------
extern "C" void kernel_launch(void* const* d_in, const int* in_sizes, int n_in,
                              void* d_out, int out_size)
{
    const float* x      = (const float*)d_in[0];
    const int*   ei     = (const int*)d_in[1];
    const float* Wq     = (const float*)d_in[3];
    const float* Wk     = (const float*)d_in[4];
    const float* Wv     = (const float*)d_in[5];
    const float* Wo_w   = (const float*)d_in[6];
    const float* Wo_b   = (const float*)d_in[7];
    const float* ln1_g  = (const float*)d_in[8];
    const float* ln1_b  = (const float*)d_in[9];
    const float* ln2_g  = (const float*)d_in[10];
    const float* ln2_b  = (const float*)d_in[11];
    const float* ffn_w1 = (const float*)d_in[12];
    const float* ffn_b1 = (const float*)d_in[13];
    const float* ffn_w2 = (const float*)d_in[14];
    const float* ffn_b2 = (const float*)d_in[15];
    float* out = (float*)d_out;

    float *pQ, *pH1;
    __half *pKV, *pXf, *pAf, *pHf, *pTf, *pW;
    cudaGetSymbolAddress((void**)&pQ,   g_Q);
    cudaGetSymbolAddress((void**)&pKV,  g_KV);
    cudaGetSymbolAddress((void**)&pH1,  g_h1);
    cudaGetSymbolAddress((void**)&pXf,  g_Xf);
    cudaGetSymbolAddress((void**)&pAf,  g_Af);
    cudaGetSymbolAddress((void**)&pHf,  g_Hf);
    cudaGetSymbolAddress((void**)&pTf,  g_Tf);
    cudaGetSymbolAddress((void**)&pW,   g_W);

    cudaFuncSetAttribute(mma_gemm<0, 0, 2>, cudaFuncAttributeMaxDynamicSharedMemorySize, GEMM_SMEM);
    cudaFuncSetAttribute(mma_gemm<1, 1, 1>, cudaFuncAttributeMaxDynamicSharedMemorySize, GEMM_SMEM);
    cudaFuncSetAttribute(mma_gemm_ln<0>, cudaFuncAttributeMaxDynamicSharedMemorySize, LN_SMEM);
    cudaFuncSetAttribute(mma_gemm_ln<1>, cudaFuncAttributeMaxDynamicSharedMemorySize, LN_SMEM);

    // lazy host-side resources (created on the first, non-captured call; reused after)
    static cudaStream_t s2 = nullptr;
    static cudaEvent_t evRoot = nullptr, evSort = nullptr;
    if (s2 == nullptr) {
        cudaStreamCreateWithFlags(&s2, cudaStreamNonBlocking);
        cudaEventCreateWithFlags(&evRoot, cudaEventDisableTiming);
        cudaEventCreateWithFlags(&evSort, cudaEventDisableTiming);
    }

    const int MT = (NN + 127) / 128;     // 391

    // ---- fork: CSR sort chain on side stream s2 ----
    cudaEventRecord(evRoot, 0);
    cudaStreamWaitEvent(s2, evRoot, 0);
    zero_cnt<<<(NN + 255) / 256, 256, 0, s2>>>();
    hist_kernel<<<(EE + 255) / 256, 256, 0, s2>>>(ei);
    scan_kernel<<<1, 1024, 0, s2>>>();
    scatter_kernel<<<(EE + 255) / 256, 256, 0, s2>>>(ei);
    cudaEventRecord(evSort, s2);

    // ---- main stream: prep + QKV (independent of sort) ----
    prep_weights<<<(W_TOT + 255) / 256, 256>>>(Wq, Wk, Wv, Wo_w, ffn_w1, ffn_w2);
    conv_f16<<<(NN * CC / 4 + 255) / 256, 256>>>(x, pXf, NN * CC / 4);
    mma_gemm<0, 0, 2><<<dim3(6, MT), 256, GEMM_SMEM>>>(
        pXf, pW + W_QKV, nullptr, pQ, nullptr, pKV, NN, 768, CC);

    // ---- join: attention needs QKV + sorted CSR ----
    cudaStreamWaitEvent(0, evSort, 0);
    attn_kernel<<<NN / 8, 256>>>(pAf);

    // Wo projection + residual(x) + LN1 -> h1 fp32 + fp16
    mma_gemm_ln<1><<<dim3(1, MT), 512, LN_SMEM>>>(
        pAf, pW + W_WO, Wo_b, x, ln1_g, ln1_b, pH1, pHf, NN, CC);

    // FFN1 + GELU -> hidden fp16
    mma_gemm<1, 1, 1><<<dim3(4, MT), 256, GEMM_SMEM>>>(
        pHf, pW + W_F1, ffn_b1, nullptr, pTf, nullptr, NN, FF, CC);

    // FFN2 + residual(h1) + LN2 -> out
    mma_gemm_ln<0><<<dim3(1, MT), 512, LN_SMEM>>>(
        pTf, pW + W_F2, ffn_b2, pH1, ln2_g, ln2_b, out, nullptr, NN, FF);
}

// round 16
// speedup vs baseline: 1.0687x; 1.0624x over previous
#include <cuda_runtime.h>
#include <cuda_fp16.h>
#include <cstdint>

#define NN 50000
#define EE 800000
#define CC 256
#define HH 8
#define DD 32
#define FF 512
#define SCALE 0.17677669529663689f

#define W_QKV 0
#define W_WO  196608
#define W_F1  262144
#define W_F2  393216
#define W_TOT 524288

// ---------------- scratch ----------------
__device__ float g_Q[(size_t)NN * CC];            // Q fp32
__device__ __half g_KV[(size_t)NN * 512];         // K|V fp16 packed per node
__device__ __half g_Xf[(size_t)NN * CC];          // x fp16
__device__ __half g_Af[(size_t)NN * CC];          // attn agg fp16
__device__ __half g_Hf[(size_t)NN * CC];          // h1 fp16 (LN1 out; also residual for LN2)
__device__ __half g_Tf[(size_t)NN * FF];          // ffn hidden fp16
__device__ __half g_W[W_TOT];                     // weights fp16, k-major
__device__ int g_cnt[NN], g_ofs[NN], g_cur[NN];
__device__ int g_ss[EE];                          // src sorted by dst

// ---------------- helpers ----------------
__device__ __forceinline__ uint32_t smem_u32(const void* p) {
    uint32_t a;
    asm("{ .reg .u64 t; cvta.to.shared.u64 t, %1; cvt.u32.u64 %0, t; }" : "=r"(a) : "l"(p));
    return a;
}
#define SWZ(off) ((off) ^ (((off) >> 3) & 0x70))

__device__ __forceinline__ void ldm_x4(uint32_t* r, uint32_t addr) {
    asm volatile("ldmatrix.sync.aligned.m8n8.x4.shared.b16 {%0,%1,%2,%3}, [%4];"
        : "=r"(r[0]), "=r"(r[1]), "=r"(r[2]), "=r"(r[3]) : "r"(addr));
}
__device__ __forceinline__ void mma_f16(float* d, const uint32_t* a, const uint32_t* b) {
    asm volatile("mma.sync.aligned.m16n8k16.row.col.f32.f16.f16.f32 "
        "{%0,%1,%2,%3}, {%4,%5,%6,%7}, {%8,%9}, {%0,%1,%2,%3};"
        : "+f"(d[0]), "+f"(d[1]), "+f"(d[2]), "+f"(d[3])
        : "r"(a[0]), "r"(a[1]), "r"(a[2]), "r"(a[3]), "r"(b[0]), "r"(b[1]));
}
__device__ __forceinline__ uint32_t f2h2(float x, float y) {
    __half2 h = __float22half2_rn(make_float2(x, y));
    return *(uint32_t*)&h;
}
__device__ __forceinline__ void cpa16(uint32_t dst, const void* src, uint32_t sz) {
    asm volatile("cp.async.cg.shared.global [%0], [%1], 16, %2;"
        :: "r"(dst), "l"(src), "r"(sz) : "memory");
}
#define CP_COMMIT() asm volatile("cp.async.commit_group;" ::: "memory")
#define CP_WAIT1()  asm volatile("cp.async.wait_group 1;" ::: "memory")

// unpack 8 fp16 (uint4) -> 8 floats
__device__ __forceinline__ void h8_to_f(const uint4& r, float* f) {
    float2 t;
    t = __half22float2(*(const __half2*)&r.x); f[0] = t.x; f[1] = t.y;
    t = __half22float2(*(const __half2*)&r.y); f[2] = t.x; f[3] = t.y;
    t = __half22float2(*(const __half2*)&r.z); f[4] = t.x; f[5] = t.y;
    t = __half22float2(*(const __half2*)&r.w); f[6] = t.x; f[7] = t.y;
}

// ---------------- weight prep: transpose to k-major fp16 ----------------
__global__ void prep_weights(const float* __restrict__ Wq, const float* __restrict__ Wk,
                             const float* __restrict__ Wv, const float* __restrict__ Wo,
                             const float* __restrict__ F1, const float* __restrict__ F2)
{
    int idx = blockIdx.x * 256 + threadIdx.x;
    if (idx >= W_TOT) return;
    float w;
    if (idx < W_WO) {
        int n = idx >> 8, k = idx & 255;
        if (n < 256)      w = Wq[k * 256 + n];
        else if (n < 512) w = Wk[k * 256 + (n - 256)];
        else              w = Wv[k * 256 + (n - 512)];
    } else if (idx < W_F1) {
        int l = idx - W_WO;
        int n = l >> 8, k = l & 255;
        w = Wo[k * 256 + n];
    } else if (idx < W_F2) {
        int l = idx - W_F1;
        int n = l >> 8, k = l & 255;
        w = F1[k * 512 + n];
    } else {
        int l = idx - W_F2;
        int n = l >> 9, k = l & 511;
        w = F2[k * 256 + n];
    }
    g_W[idx] = __float2half(w);
}

// ---------------- fp32 -> fp16 convert (vectorized) ----------------
__global__ void conv_f16(const float* __restrict__ in, __half* __restrict__ o, int n4)
{
    int i = blockIdx.x * 256 + threadIdx.x;
    if (i >= n4) return;
    float4 v = ((const float4*)in)[i];
    ((uint2*)o)[i] = make_uint2(f2h2(v.x, v.y), f2h2(v.z, v.w));
}

// ---------------- pipelined fp16 GEMM (2-stage, R12-proven) ----------------
// OMODE: 0 = fp32 C; 1 = fp16 Cf; 2 = QKV mixed (Q fp32, K|V fp16)
#define STG 32768
#define GEMM_SMEM (2 * STG)

template<int BIAS, int GELU, int OMODE>
__global__ __launch_bounds__(256, 2) void mma_gemm(
    const __half* __restrict__ Ag, const __half* __restrict__ Bg,
    const float* __restrict__ bias, float* __restrict__ C,
    __half* __restrict__ Cf, __half* __restrict__ KV,
    int M, int N, int K)
{
    extern __shared__ char smem[];
    uint32_t sb = smem_u32(smem);
    int tid = threadIdx.x, wid = tid >> 5, lane = tid & 31;
    int row0 = blockIdx.y * 128;
    int col0 = blockIdx.x * 128;
    int Am0 = (wid >> 2) * 64;
    int Bn0 = (wid & 3) * 32;

    uint32_t arow[4], brow[2];
#pragma unroll
    for (int mt = 0; mt < 4; mt++)
        arow[mt] = (uint32_t)((Am0 + mt * 16 + (lane & 15)) * 128 + (lane >> 4) * 16);
#pragma unroll
    for (int ntp = 0; ntp < 2; ntp++)
        brow[ntp] = (uint32_t)((Bn0 + ntp * 16 + (lane >> 4) * 8 + (lane & 7)) * 128
                               + ((lane >> 3) & 1) * 16);

    float d[4][4][4];
#pragma unroll
    for (int i = 0; i < 4; i++)
#pragma unroll
        for (int j = 0; j < 4; j++)
#pragma unroll
            for (int e = 0; e < 4; e++) d[i][j][e] = 0.f;

    auto load_stage = [&](int st, int kt) {
        uint32_t base = sb + st * STG;
#pragma unroll
        for (int j = 0; j < 4; j++) {
            int id = tid + 256 * j;
            int r = id >> 3, c = id & 7;
            uint32_t off = SWZ((uint32_t)(r * 128 + c * 16));
            int gr = row0 + r;
            uint32_t sz = (gr < M) ? 16u : 0u;
            int grc = (gr < M) ? gr : (M - 1);
            cpa16(base + off, Ag + (size_t)grc * K + kt + c * 8, sz);
            int gn = col0 + r;
            cpa16(base + 16384 + off, Bg + (size_t)gn * K + kt + c * 8, 16u);
        }
    };

    load_stage(0, 0);
    CP_COMMIT();

    const int nIter = K >> 6;
    for (int it = 0; it < nIter; ++it) {
        if (it + 1 < nIter) load_stage((it + 1) & 1, (it + 1) << 6);
        CP_COMMIT();
        CP_WAIT1();
        __syncthreads();

        uint32_t sA = sb + (it & 1) * STG;
        uint32_t sB = sA + 16384;
#pragma unroll
        for (int ks = 0; ks < 4; ks++) {
            uint32_t aF[4][4], bF[4][2];
#pragma unroll
            for (int mt = 0; mt < 4; mt++)
                ldm_x4(aF[mt], sA + SWZ(arow[mt] + ks * 32));
#pragma unroll
            for (int ntp = 0; ntp < 2; ntp++)
                ldm_x4(&bF[ntp * 2][0], sB + SWZ(brow[ntp] + ks * 32));
#pragma unroll
            for (int mt = 0; mt < 4; mt++)
#pragma unroll
                for (int nt = 0; nt < 4; nt++)
                    mma_f16(d[mt][nt], aF[mt], bF[nt]);
        }
        __syncthreads();
    }

#pragma unroll
    for (int nt = 0; nt < 4; nt++) {
        int c = col0 + Bn0 + nt * 8 + (lane & 3) * 2;
        float b0 = 0.f, b1 = 0.f;
        if (BIAS) { b0 = bias[c]; b1 = bias[c + 1]; }
#pragma unroll
        for (int mt = 0; mt < 4; mt++) {
            int r0 = row0 + Am0 + mt * 16 + (lane >> 2);
#pragma unroll
            for (int half = 0; half < 2; half++) {
                int r = r0 + half * 8;
                if (r < M) {
                    float v0 = d[mt][nt][half * 2 + 0] + b0;
                    float v1 = d[mt][nt][half * 2 + 1] + b1;
                    if (GELU) {
                        v0 = 0.5f * v0 * (1.f + erff(v0 * 0.70710678118654752f));
                        v1 = 0.5f * v1 * (1.f + erff(v1 * 0.70710678118654752f));
                    }
                    if (OMODE == 1) {
                        *(uint32_t*)(Cf + (size_t)r * N + c) = f2h2(v0, v1);
                    } else if (OMODE == 2) {
                        if (col0 < 256) {
                            *(float2*)(C + (size_t)r * CC + c) = make_float2(v0, v1);
                        } else {
                            *(uint32_t*)(KV + (size_t)r * 512 + (c - 256)) = f2h2(v0, v1);
                        }
                    } else {
                        *(float2*)(C + (size_t)r * N + c) = make_float2(v0, v1);
                    }
                }
            }
        }
    }
}

// ---------------- GEMM + residual(fp16) + LayerNorm fused ----------------
// SPLIT=1: write fp16 Of only (LN1).  SPLIT=0: write fp32 Out only (LN2 -> d_out).
#define LSTG 49152
#define LN_SMEM (2 * LSTG)

template<int SPLIT>
__global__ __launch_bounds__(512, 1) void mma_gemm_ln(
    const __half* __restrict__ Ag, const __half* __restrict__ Bg,
    const float* __restrict__ bias, const __half* __restrict__ Res,
    const float* __restrict__ lnG, const float* __restrict__ lnB,
    float* __restrict__ Out, __half* __restrict__ Of,
    int M, int K)
{
    extern __shared__ char smem[];
    uint32_t sb = smem_u32(smem);
    int tid = threadIdx.x, wid = tid >> 5, lane = tid & 31;
    int row0 = blockIdx.y * 128;
    int wM = wid >> 2, wN = wid & 3;
    int Am0 = wM * 32;
    int Bn0 = wN * 64;

    uint32_t arow[2], brow[4];
#pragma unroll
    for (int mt = 0; mt < 2; mt++)
        arow[mt] = (uint32_t)((Am0 + mt * 16 + (lane & 15)) * 128 + (lane >> 4) * 16);
#pragma unroll
    for (int ntp = 0; ntp < 4; ntp++)
        brow[ntp] = (uint32_t)((Bn0 + ntp * 16 + (lane >> 4) * 8 + (lane & 7)) * 128
                               + ((lane >> 3) & 1) * 16);

    float d[2][8][4];
#pragma unroll
    for (int i = 0; i < 2; i++)
#pragma unroll
        for (int j = 0; j < 8; j++)
#pragma unroll
            for (int e = 0; e < 4; e++) d[i][j][e] = 0.f;

    auto load_stage = [&](int st, int kt) {
        uint32_t base = sb + st * LSTG;
#pragma unroll
        for (int j = 0; j < 2; j++) {
            int id = tid + 512 * j;
            int r = id >> 3, c = id & 7;
            uint32_t off = SWZ((uint32_t)(r * 128 + c * 16));
            int gr = row0 + r;
            uint32_t sz = (gr < M) ? 16u : 0u;
            int grc = (gr < M) ? gr : (M - 1);
            cpa16(base + off, Ag + (size_t)grc * K + kt + c * 8, sz);
        }
#pragma unroll
        for (int j = 0; j < 4; j++) {
            int id = tid + 512 * j;
            int r = id >> 3, c = id & 7;
            uint32_t off = SWZ((uint32_t)(r * 128 + c * 16));
            cpa16(base + 16384 + off, Bg + (size_t)r * K + kt + c * 8, 16u);
        }
    };

    load_stage(0, 0);
    CP_COMMIT();

    const int nIter = K >> 6;
    for (int it = 0; it < nIter; ++it) {
        if (it + 1 < nIter) load_stage((it + 1) & 1, (it + 1) << 6);
        CP_COMMIT();
        CP_WAIT1();
        __syncthreads();

        uint32_t sA = sb + (it & 1) * LSTG;
        uint32_t sB = sA + 16384;
#pragma unroll
        for (int ks = 0; ks < 4; ks++) {
            uint32_t aF[2][4], bF[8][2];
#pragma unroll
            for (int mt = 0; mt < 2; mt++)
                ldm_x4(aF[mt], sA + SWZ(arow[mt] + ks * 32));
#pragma unroll
            for (int ntp = 0; ntp < 4; ntp++)
                ldm_x4(&bF[ntp * 2][0], sB + SWZ(brow[ntp] + ks * 32));
#pragma unroll
            for (int mt = 0; mt < 2; mt++)
#pragma unroll
                for (int nt = 0; nt < 8; nt++)
                    mma_f16(d[mt][nt], aF[mt], bF[nt]);
        }
        __syncthreads();
    }

    float* part = (float*)smem;
    float psum[2][2], psq[2][2];
#pragma unroll
    for (int mt = 0; mt < 2; mt++)
#pragma unroll
    for (int half = 0; half < 2; half++) {
        int lr = Am0 + mt * 16 + (lane >> 2) + half * 8;
        int r = row0 + lr;
        float s = 0.f, q = 0.f;
#pragma unroll
        for (int nt = 0; nt < 8; nt++) {
            int c = Bn0 + nt * 8 + (lane & 3) * 2;
            float2 res = make_float2(0.f, 0.f);
            if (r < M) {
                uint32_t rr = *(const uint32_t*)(Res + (size_t)r * CC + c);
                res = __half22float2(*(const __half2*)&rr);
            }
            float v0 = d[mt][nt][half * 2 + 0] + bias[c] + res.x;
            float v1 = d[mt][nt][half * 2 + 1] + bias[c + 1] + res.y;
            d[mt][nt][half * 2 + 0] = v0;
            d[mt][nt][half * 2 + 1] = v1;
            s += v0 + v1;
            q += v0 * v0 + v1 * v1;
        }
        s += __shfl_xor_sync(0xffffffffu, s, 1);
        q += __shfl_xor_sync(0xffffffffu, q, 1);
        s += __shfl_xor_sync(0xffffffffu, s, 2);
        q += __shfl_xor_sync(0xffffffffu, q, 2);
        psum[mt][half] = s;
        psq[mt][half] = q;
    }
    if ((lane & 3) == 0) {
#pragma unroll
        for (int mt = 0; mt < 2; mt++)
#pragma unroll
        for (int half = 0; half < 2; half++) {
            int lr = Am0 + mt * 16 + (lane >> 2) + half * 8;
            part[(lr * 4 + wN) * 2 + 0] = psum[mt][half];
            part[(lr * 4 + wN) * 2 + 1] = psq[mt][half];
        }
    }
    __syncthreads();

#pragma unroll
    for (int mt = 0; mt < 2; mt++)
#pragma unroll
    for (int half = 0; half < 2; half++) {
        int lr = Am0 + mt * 16 + (lane >> 2) + half * 8;
        int r = row0 + lr;
        if (r >= M) continue;
        float S = part[(lr * 4 + 0) * 2] + part[(lr * 4 + 1) * 2]
                + part[(lr * 4 + 2) * 2] + part[(lr * 4 + 3) * 2];
        float Q = part[(lr * 4 + 0) * 2 + 1] + part[(lr * 4 + 1) * 2 + 1]
                + part[(lr * 4 + 2) * 2 + 1] + part[(lr * 4 + 3) * 2 + 1];
        float mu = S * (1.f / 256.f);
        float var = Q * (1.f / 256.f) - mu * mu;
        float rs = rsqrtf(var + 1e-5f);
#pragma unroll
        for (int nt = 0; nt < 8; nt++) {
            int c = Bn0 + nt * 8 + (lane & 3) * 2;
            float o0 = (d[mt][nt][half * 2 + 0] - mu) * rs * lnG[c] + lnB[c];
            float o1 = (d[mt][nt][half * 2 + 1] - mu) * rs * lnG[c + 1] + lnB[c + 1];
            if (SPLIT)
                *(uint32_t*)(Of + (size_t)r * CC + c) = f2h2(o0, o1);
            else
                *(float2*)(Out + (size_t)r * CC + c) = make_float2(o0, o1);
        }
    }
}

// ---------------- CSR sort: hist -> scan -> scatter ----------------
__global__ void zero_cnt() {
    int i = blockIdx.x * 256 + threadIdx.x;
    if (i < NN) g_cnt[i] = 0;
}
__global__ void hist_kernel(const int* __restrict__ ei) {
    int e = blockIdx.x * 256 + threadIdx.x;
    if (e < EE) atomicAdd(&g_cnt[ei[EE + e]], 1);
}
__global__ __launch_bounds__(1024) void scan_kernel() {
    __shared__ int part[1024];
    const int CH = 49;
    int t = threadIdx.x;
    int base = t * CH;
    int s = 0;
    for (int j = 0; j < CH; j++) {
        int i = base + j;
        if (i < NN) s += g_cnt[i];
    }
    part[t] = s;
    __syncthreads();
    for (int off = 1; off < 1024; off <<= 1) {
        int v = (t >= off) ? part[t - off] : 0;
        __syncthreads();
        part[t] += v;
        __syncthreads();
    }
    int run = (t == 0) ? 0 : part[t - 1];
    for (int j = 0; j < CH; j++) {
        int i = base + j;
        if (i < NN) {
            g_ofs[i] = run;
            g_cur[i] = run;
            run += g_cnt[i];
        }
    }
}
__global__ void scatter_kernel(const int* __restrict__ ei) {
    int e = blockIdx.x * 256 + threadIdx.x;
    if (e >= EE) return;
    int dst = ei[EE + e];
    int pos = atomicAdd(&g_cur[dst], 1);
    g_ss[pos] = ei[e];
}

// ---------------- fused per-dst attention (R12-proven 2-wide online softmax) ----------------
__global__ __launch_bounds__(256) void attn_kernel(__half* __restrict__ of)
{
    int tid = threadIdx.x;
    int w = tid >> 5, lane = tid & 31;
    int h = lane >> 2, sub = lane & 3;
    int dst = blockIdx.x * 8 + w;

    const float* qp = g_Q + (size_t)dst * CC + h * DD + sub * 8;
    float4 q0 = ((const float4*)qp)[0], q1 = ((const float4*)qp)[1];
    const float* qf0 = &q0.x;
    const float* qf1 = &q1.x;
    int beg = g_ofs[dst], cnt = g_cnt[dst];

    float m = 0.f, sum = 0.f;
    float a[8];
#pragma unroll
    for (int e = 0; e < 8; e++) a[e] = 0.f;

    int i = 0;
    for (; i + 1 < cnt; i += 2) {
        int s0 = g_ss[beg + i], s1 = g_ss[beg + i + 1];
        const __half* b0p = g_KV + (size_t)s0 * 512 + h * DD + sub * 8;
        const __half* b1p = g_KV + (size_t)s1 * 512 + h * DD + sub * 8;
        uint4 k0r = *(const uint4*)b0p;
        uint4 k1r = *(const uint4*)b1p;
        uint4 v0r = *(const uint4*)(b0p + 256);
        uint4 v1r = *(const uint4*)(b1p + 256);
        float kf0[8], kf1[8], vf0[8], vf1[8];
        h8_to_f(k0r, kf0); h8_to_f(k1r, kf1);
        h8_to_f(v0r, vf0); h8_to_f(v1r, vf1);
        float d0 = 0.f, d1 = 0.f;
#pragma unroll
        for (int e = 0; e < 4; e++) {
            d0 += qf0[e] * kf0[e] + qf1[e] * kf0[4 + e];
            d1 += qf0[e] * kf1[e] + qf1[e] * kf1[4 + e];
        }
        d0 += __shfl_xor_sync(0xffffffffu, d0, 1);
        d1 += __shfl_xor_sync(0xffffffffu, d1, 1);
        d0 += __shfl_xor_sync(0xffffffffu, d0, 2);
        d1 += __shfl_xor_sync(0xffffffffu, d1, 2);
        float sa = d0 * SCALE, sb2 = d1 * SCALE;
        float nm = fmaxf(m, fmaxf(sa, sb2));
        float f  = __expf(m - nm);
        float wa = __expf(sa - nm), wb = __expf(sb2 - nm);
        m = nm;
        sum = sum * f + wa + wb;
#pragma unroll
        for (int e = 0; e < 8; e++)
            a[e] = a[e] * f + wa * vf0[e] + wb * vf1[e];
    }
    if (i < cnt) {
        int s0 = g_ss[beg + i];
        const __half* b0p = g_KV + (size_t)s0 * 512 + h * DD + sub * 8;
        uint4 k0r = *(const uint4*)b0p;
        uint4 v0r = *(const uint4*)(b0p + 256);
        float kf0[8], vf0[8];
        h8_to_f(k0r, kf0);
        h8_to_f(v0r, vf0);
        float d0 = 0.f;
#pragma unroll
        for (int e = 0; e < 4; e++)
            d0 += qf0[e] * kf0[e] + qf1[e] * kf0[4 + e];
        d0 += __shfl_xor_sync(0xffffffffu, d0, 1);
        d0 += __shfl_xor_sync(0xffffffffu, d0, 2);
        float sa = d0 * SCALE;
        float nm = fmaxf(m, sa);
        float f  = __expf(m - nm);
        float wa = __expf(sa - nm);
        m = nm;
        sum = sum * f + wa;
#pragma unroll
        for (int e = 0; e < 8; e++)
            a[e] = a[e] * f + wa * vf0[e];
    }

    float inv = 1.f / (sum + 1e-8f);
    uint4 o;
    o.x = f2h2(a[0] * inv, a[1] * inv);
    o.y = f2h2(a[2] * inv, a[3] * inv);
    o.z = f2h2(a[4] * inv, a[5] * inv);
    o.w = f2h2(a[6] * inv, a[7] * inv);
    *(uint4*)(of + (size_t)dst * CC + h * DD + sub * 8) = o;
}

// ---------------- launch (R12 topology) ----------------
extern "C" void kernel_launch(void* const* d_in, const int* in_sizes, int n_in,
                              void* d_out, int out_size)
{
    const float* x      = (const float*)d_in[0];
    const int*   ei     = (const int*)d_in[1];
    const float* Wq     = (const float*)d_in[3];
    const float* Wk     = (const float*)d_in[4];
    const float* Wv     = (const float*)d_in[5];
    const float* Wo_w   = (const float*)d_in[6];
    const float* Wo_b   = (const float*)d_in[7];
    const float* ln1_g  = (const float*)d_in[8];
    const float* ln1_b  = (const float*)d_in[9];
    const float* ln2_g  = (const float*)d_in[10];
    const float* ln2_b  = (const float*)d_in[11];
    const float* ffn_w1 = (const float*)d_in[12];
    const float* ffn_b1 = (const float*)d_in[13];
    const float* ffn_w2 = (const float*)d_in[14];
    const float* ffn_b2 = (const float*)d_in[15];
    float* out = (float*)d_out;

    float* pQ;
    __half *pKV, *pXf, *pAf, *pHf, *pTf, *pW;
    cudaGetSymbolAddress((void**)&pQ,   g_Q);
    cudaGetSymbolAddress((void**)&pKV,  g_KV);
    cudaGetSymbolAddress((void**)&pXf,  g_Xf);
    cudaGetSymbolAddress((void**)&pAf,  g_Af);
    cudaGetSymbolAddress((void**)&pHf,  g_Hf);
    cudaGetSymbolAddress((void**)&pTf,  g_Tf);
    cudaGetSymbolAddress((void**)&pW,   g_W);

    cudaFuncSetAttribute(mma_gemm<0, 0, 2>, cudaFuncAttributeMaxDynamicSharedMemorySize, GEMM_SMEM);
    cudaFuncSetAttribute(mma_gemm<1, 1, 1>, cudaFuncAttributeMaxDynamicSharedMemorySize, GEMM_SMEM);
    cudaFuncSetAttribute(mma_gemm_ln<0>, cudaFuncAttributeMaxDynamicSharedMemorySize, LN_SMEM);
    cudaFuncSetAttribute(mma_gemm_ln<1>, cudaFuncAttributeMaxDynamicSharedMemorySize, LN_SMEM);

    // lazy host-side resources (created on the first, non-captured call; reused after)
    static cudaStream_t s2 = nullptr;
    static cudaEvent_t evRoot = nullptr, evSort = nullptr;
    if (s2 == nullptr) {
        cudaStreamCreateWithFlags(&s2, cudaStreamNonBlocking);
        cudaEventCreateWithFlags(&evRoot, cudaEventDisableTiming);
        cudaEventCreateWithFlags(&evSort, cudaEventDisableTiming);
    }

    const int MT = (NN + 127) / 128;     // 391

    // ---- fork: CSR sort chain on side stream s2 ----
    cudaEventRecord(evRoot, 0);
    cudaStreamWaitEvent(s2, evRoot, 0);
    zero_cnt<<<(NN + 255) / 256, 256, 0, s2>>>();
    hist_kernel<<<(EE + 255) / 256, 256, 0, s2>>>(ei);
    scan_kernel<<<1, 1024, 0, s2>>>();
    scatter_kernel<<<(EE + 255) / 256, 256, 0, s2>>>(ei);
    cudaEventRecord(evSort, s2);

    // ---- main stream: prep + QKV (independent of sort) ----
    prep_weights<<<(W_TOT + 255) / 256, 256>>>(Wq, Wk, Wv, Wo_w, ffn_w1, ffn_w2);
    conv_f16<<<(NN * CC / 4 + 255) / 256, 256>>>(x, pXf, NN * CC / 4);
    mma_gemm<0, 0, 2><<<dim3(6, MT), 256, GEMM_SMEM>>>(
        pXf, pW + W_QKV, nullptr, pQ, nullptr, pKV, NN, 768, CC);

    // ---- join: attention needs QKV + sorted CSR ----
    cudaStreamWaitEvent(0, evSort, 0);
    attn_kernel<<<NN / 8, 256>>>(pAf);

    // Wo projection + residual(x fp16) + LN1 -> h1 fp16
    mma_gemm_ln<1><<<dim3(1, MT), 512, LN_SMEM>>>(
        pAf, pW + W_WO, Wo_b, pXf, ln1_g, ln1_b, nullptr, pHf, NN, CC);

    // FFN1 + GELU -> hidden fp16
    mma_gemm<1, 1, 1><<<dim3(4, MT), 256, GEMM_SMEM>>>(
        pHf, pW + W_F1, ffn_b1, nullptr, pTf, nullptr, NN, FF, CC);

    // FFN2 + residual(h1 fp16) + LN2 -> out fp32
    mma_gemm_ln<0><<<dim3(1, MT), 512, LN_SMEM>>>(
        pTf, pW + W_F2, ffn_b2, pHf, ln2_g, ln2_b, out, nullptr, NN, FF);
}